// round 1
// baseline (speedup 1.0000x reference)
#include <cuda_runtime.h>

#define BATCH  4
#define SEQ    2048
#define DMODEL 1024
#define NHEADS 16
#define HDIM   64
#define MROWS  (BATCH * SEQ)   // 8192

// Scratch (device globals: no allocation allowed in kernel_launch)
__device__ float g_Q[(size_t)BATCH * NHEADS * SEQ * HDIM];   // [b,h,n,hd]
__device__ float g_K[(size_t)BATCH * NHEADS * SEQ * HDIM];
__device__ float g_V[(size_t)BATCH * NHEADS * SEQ * HDIM];
__device__ float g_ctx[(size_t)MROWS * DMODEL];              // [b,n,d]

// ======================================================================
// Kernel 1: QKV projections.  C = X @ W, scattered to [b,h,n,hd].
// 128x128 tile, BK=8, 256 threads, 8x8 micro-tile.
// ======================================================================
__global__ __launch_bounds__(256) void qkv_gemm(const float* __restrict__ X,
                                                const float* __restrict__ Wq,
                                                const float* __restrict__ Wk,
                                                const float* __restrict__ Wv) {
    __shared__ float As[8][128];
    __shared__ float Bs[8][128];
    const int tid = threadIdx.x;
    const int mat = blockIdx.z;
    const float* __restrict__ W   = (mat == 0) ? Wq : (mat == 1 ? Wk : Wv);
    float* __restrict__       Out = (mat == 0) ? g_Q : (mat == 1 ? g_K : g_V);
    const int bm = blockIdx.y * 128;
    const int bn = blockIdx.x * 128;

    const int aRow = tid >> 1;
    const int aCol = (tid & 1) << 2;
    const int bRow = tid >> 5;
    const int bCol = (tid & 31) << 2;
    const int tr = (tid >> 4) << 3;
    const int tc = (tid & 15) << 3;

    float acc[8][8];
#pragma unroll
    for (int i = 0; i < 8; i++)
#pragma unroll
        for (int j = 0; j < 8; j++) acc[i][j] = 0.f;

    const float* Ap = X + (size_t)(bm + aRow) * DMODEL + aCol;
    const float* Bp = W + (size_t)bRow * DMODEL + bn + bCol;

    for (int k0 = 0; k0 < DMODEL; k0 += 8) {
        float4 av = *(const float4*)(Ap + k0);
        float4 bv = *(const float4*)(Bp + (size_t)k0 * DMODEL);
        As[aCol + 0][aRow] = av.x;
        As[aCol + 1][aRow] = av.y;
        As[aCol + 2][aRow] = av.z;
        As[aCol + 3][aRow] = av.w;
        *(float4*)&Bs[bRow][bCol] = bv;
        __syncthreads();
#pragma unroll
        for (int kk = 0; kk < 8; kk++) {
            float a[8], b[8];
            *(float4*)(a)     = *(const float4*)&As[kk][tr];
            *(float4*)(a + 4) = *(const float4*)&As[kk][tr + 4];
            *(float4*)(b)     = *(const float4*)&Bs[kk][tc];
            *(float4*)(b + 4) = *(const float4*)&Bs[kk][tc + 4];
#pragma unroll
            for (int i = 0; i < 8; i++)
#pragma unroll
                for (int j = 0; j < 8; j++)
                    acc[i][j] = fmaf(a[i], b[j], acc[i][j]);
        }
        __syncthreads();
    }

#pragma unroll
    for (int i = 0; i < 8; i++) {
        int r = bm + tr + i;
        int b = r >> 11;             // / SEQ
        int n = r & (SEQ - 1);
#pragma unroll
        for (int j = 0; j < 8; j++) {
            int c  = bn + tc + j;
            int h  = c >> 6;
            int hd = c & 63;
            Out[(((size_t)b * NHEADS + h) * SEQ + n) * HDIM + hd] = acc[i][j];
        }
    }
}

// ======================================================================
// Kernel 2: flash attention (causal), one (q-tile, b*h) per block.
// BQ = BKV = 64, 256 threads, 4x4 register micro-tiles for both GEMMs.
// Dynamic smem: Qt[64][64] (d-major), Kt[64][64] (d-major),
//               Vs[64][64] (j-major), Pt[64][65] (j-major, padded).
// ======================================================================
__global__ __launch_bounds__(256) void flash_attn() {
    extern __shared__ float sm[];
    float* Qt   = sm;                 // Qt[d*64 + i]
    float* Kt   = Qt + 64 * 64;       // Kt[d*64 + j]
    float* Vs   = Kt + 64 * 64;       // Vs[j*64 + d]
    float* Pt   = Vs + 64 * 64;       // Pt[j*65 + i]
    float* m_s  = Pt + 64 * 65;
    float* l_s  = m_s + 64;
    float* al_s = l_s + 64;

    const int tid = threadIdx.x;
    const int qt  = blockIdx.x;       // query tile (32 of them)
    const int bh  = blockIdx.y;       // b*16 + h
    const float* __restrict__ Qg = g_Q + (size_t)bh * SEQ * HDIM;
    const float* __restrict__ Kg = g_K + (size_t)bh * SEQ * HDIM;
    const float* __restrict__ Vg = g_V + (size_t)bh * SEQ * HDIM;

    const int i0 = (tid >> 4) << 2;   // micro-tile rows   0..60
    const int c0 = (tid & 15) << 2;   // micro-tile cols   0..60

    // ---- load Q tile transposed (once per block) ----
    {
        const float* src = Qg + (size_t)qt * 64 * HDIM;
#pragma unroll
        for (int r = 0; r < 4; r++) {
            int q   = r * 256 + tid;     // float4 index 0..1023
            int row = q >> 4;
            int cc  = (q & 15) << 2;
            float4 v = *(const float4*)(src + row * HDIM + cc);
            Qt[(cc + 0) * 64 + row] = v.x;
            Qt[(cc + 1) * 64 + row] = v.y;
            Qt[(cc + 2) * 64 + row] = v.z;
            Qt[(cc + 3) * 64 + row] = v.w;
        }
    }
    if (tid < 64) { m_s[tid] = -1e30f; l_s[tid] = 0.f; }

    float o[4][4];
#pragma unroll
    for (int ii = 0; ii < 4; ii++)
#pragma unroll
        for (int jj = 0; jj < 4; jj++) o[ii][jj] = 0.f;

    const float scale = 0.125f;       // 1/sqrt(64)
    const int ktiles = qt + 1;        // causal: only tiles up to diagonal

    for (int kt = 0; kt < ktiles; kt++) {
        __syncthreads();              // protect Kt/Vs/Pt reuse (+ first-iter init)

        // ---- load K (transposed) and V tiles ----
        const float* ks   = Kg + (size_t)kt * 64 * HDIM;
        const float* vsrc = Vg + (size_t)kt * 64 * HDIM;
#pragma unroll
        for (int r = 0; r < 4; r++) {
            int q   = r * 256 + tid;
            int row = q >> 4;
            int cc  = (q & 15) << 2;
            float4 v = *(const float4*)(ks + row * HDIM + cc);
            Kt[(cc + 0) * 64 + row] = v.x;
            Kt[(cc + 1) * 64 + row] = v.y;
            Kt[(cc + 2) * 64 + row] = v.z;
            Kt[(cc + 3) * 64 + row] = v.w;
            float4 w = *(const float4*)(vsrc + row * HDIM + cc);
            *(float4*)&Vs[row * 64 + cc] = w;
        }
        __syncthreads();

        // ---- S = Q @ K^T (4x4 per thread) ----
        float s[4][4];
#pragma unroll
        for (int ii = 0; ii < 4; ii++)
#pragma unroll
            for (int jj = 0; jj < 4; jj++) s[ii][jj] = 0.f;
#pragma unroll
        for (int d = 0; d < HDIM; d++) {
            float4 qv = *(const float4*)&Qt[d * 64 + i0];
            float4 kv = *(const float4*)&Kt[d * 64 + c0];
            float qa[4] = {qv.x, qv.y, qv.z, qv.w};
            float ka[4] = {kv.x, kv.y, kv.z, kv.w};
#pragma unroll
            for (int ii = 0; ii < 4; ii++)
#pragma unroll
                for (int jj = 0; jj < 4; jj++)
                    s[ii][jj] = fmaf(qa[ii], ka[jj], s[ii][jj]);
        }

        // ---- scale + causal mask, write transposed to Pt ----
        const int qbase = qt * 64 + i0;
        const int kbase = kt * 64 + c0;
#pragma unroll
        for (int ii = 0; ii < 4; ii++)
#pragma unroll
            for (int jj = 0; jj < 4; jj++) {
                float v = s[ii][jj] * scale;
                if (kbase + jj > qbase + ii) v = -1e30f;
                Pt[(c0 + jj) * 65 + (i0 + ii)] = v;
            }
        __syncthreads();

        // ---- online softmax: 4 threads per row, shfl combine ----
        {
            const int i  = tid >> 2;
            const int qq = tid & 3;
            float mt = -1e30f;
#pragma unroll
            for (int j = qq * 16; j < qq * 16 + 16; j++)
                mt = fmaxf(mt, Pt[j * 65 + i]);
            mt = fmaxf(mt, __shfl_xor_sync(0xffffffffu, mt, 1));
            mt = fmaxf(mt, __shfl_xor_sync(0xffffffffu, mt, 2));
            float m_old = m_s[i];
            float mnew  = fmaxf(m_old, mt);
            float lsum  = 0.f;
#pragma unroll
            for (int j = qq * 16; j < qq * 16 + 16; j++) {
                float p = __expf(Pt[j * 65 + i] - mnew);
                Pt[j * 65 + i] = p;
                lsum += p;
            }
            lsum += __shfl_xor_sync(0xffffffffu, lsum, 1);
            lsum += __shfl_xor_sync(0xffffffffu, lsum, 2);
            if (qq == 0) {
                float alpha = __expf(m_old - mnew);
                l_s[i]  = l_s[i] * alpha + lsum;
                m_s[i]  = mnew;
                al_s[i] = alpha;
            }
        }
        __syncthreads();

        // ---- rescale O, then O += P @ V (4x4 per thread) ----
#pragma unroll
        for (int ii = 0; ii < 4; ii++) {
            float al = al_s[i0 + ii];
#pragma unroll
            for (int jj = 0; jj < 4; jj++) o[ii][jj] *= al;
        }
#pragma unroll
        for (int j = 0; j < 64; j++) {
            float p[4];
#pragma unroll
            for (int ii = 0; ii < 4; ii++) p[ii] = Pt[j * 65 + i0 + ii];
            float4 vv = *(const float4*)&Vs[j * 64 + c0];
            float va[4] = {vv.x, vv.y, vv.z, vv.w};
#pragma unroll
            for (int ii = 0; ii < 4; ii++)
#pragma unroll
                for (int jj = 0; jj < 4; jj++)
                    o[ii][jj] = fmaf(p[ii], va[jj], o[ii][jj]);
        }
    }

    // ---- normalize & write ctx [b,n,d] ----
    const int b = bh >> 4;
    const int h = bh & 15;
#pragma unroll
    for (int ii = 0; ii < 4; ii++) {
        float inv = 1.f / l_s[i0 + ii];
        int n = qt * 64 + i0 + ii;
        float4 w;
        w.x = o[ii][0] * inv;
        w.y = o[ii][1] * inv;
        w.z = o[ii][2] * inv;
        w.w = o[ii][3] * inv;
        *(float4*)&g_ctx[((size_t)b * SEQ + n) * DMODEL + h * HDIM + c0] = w;
    }
}

// ======================================================================
// Kernel 3: out = ctx @ Wo + bo, row-major [8192, 1024].
// ======================================================================
__global__ __launch_bounds__(256) void out_gemm(const float* __restrict__ Wo,
                                                const float* __restrict__ bo,
                                                float* __restrict__ Out) {
    __shared__ float As[8][128];
    __shared__ float Bs[8][128];
    const int tid = threadIdx.x;
    const int bm = blockIdx.y * 128;
    const int bn = blockIdx.x * 128;

    const int aRow = tid >> 1;
    const int aCol = (tid & 1) << 2;
    const int bRow = tid >> 5;
    const int bCol = (tid & 31) << 2;
    const int tr = (tid >> 4) << 3;
    const int tc = (tid & 15) << 3;

    float acc[8][8];
#pragma unroll
    for (int i = 0; i < 8; i++)
#pragma unroll
        for (int j = 0; j < 8; j++) acc[i][j] = 0.f;

    const float* Ap = g_ctx + (size_t)(bm + aRow) * DMODEL + aCol;
    const float* Bp = Wo + (size_t)bRow * DMODEL + bn + bCol;

    for (int k0 = 0; k0 < DMODEL; k0 += 8) {
        float4 av = *(const float4*)(Ap + k0);
        float4 bv = *(const float4*)(Bp + (size_t)k0 * DMODEL);
        As[aCol + 0][aRow] = av.x;
        As[aCol + 1][aRow] = av.y;
        As[aCol + 2][aRow] = av.z;
        As[aCol + 3][aRow] = av.w;
        *(float4*)&Bs[bRow][bCol] = bv;
        __syncthreads();
#pragma unroll
        for (int kk = 0; kk < 8; kk++) {
            float a[8], b[8];
            *(float4*)(a)     = *(const float4*)&As[kk][tr];
            *(float4*)(a + 4) = *(const float4*)&As[kk][tr + 4];
            *(float4*)(b)     = *(const float4*)&Bs[kk][tc];
            *(float4*)(b + 4) = *(const float4*)&Bs[kk][tc + 4];
#pragma unroll
            for (int i = 0; i < 8; i++)
#pragma unroll
                for (int j = 0; j < 8; j++)
                    acc[i][j] = fmaf(a[i], b[j], acc[i][j]);
        }
        __syncthreads();
    }

    float bias[8];
#pragma unroll
    for (int j = 0; j < 8; j++) bias[j] = bo[bn + tc + j];

#pragma unroll
    for (int i = 0; i < 8; i++) {
        size_t r = bm + tr + i;
#pragma unroll
        for (int j = 0; j < 8; j += 4) {
            int c = bn + tc + j;
            float4 w;
            w.x = acc[i][j + 0] + bias[j + 0];
            w.y = acc[i][j + 1] + bias[j + 1];
            w.z = acc[i][j + 2] + bias[j + 2];
            w.w = acc[i][j + 3] + bias[j + 3];
            *(float4*)&Out[r * DMODEL + c] = w;
        }
    }
}

// ======================================================================
extern "C" void kernel_launch(void* const* d_in, const int* in_sizes, int n_in,
                              void* d_out, int out_size) {
    (void)in_sizes; (void)n_in; (void)out_size;
    const float* x  = (const float*)d_in[0];
    const float* Wq = (const float*)d_in[1];
    const float* Wk = (const float*)d_in[2];
    const float* Wv = (const float*)d_in[3];
    const float* Wo = (const float*)d_in[4];
    const float* bo = (const float*)d_in[5];
    float* out = (float*)d_out;

    // flash_attn dynamic smem: (3*4096 + 64*65 + 192) floats = 66560 bytes
    const int flash_smem = (3 * 64 * 64 + 64 * 65 + 3 * 64) * (int)sizeof(float);
    cudaFuncSetAttribute(flash_attn, cudaFuncAttributeMaxDynamicSharedMemorySize,
                         flash_smem);

    qkv_gemm<<<dim3(DMODEL / 128, MROWS / 128, 3), 256>>>(x, Wq, Wk, Wv);
    flash_attn<<<dim3(SEQ / 64, BATCH * NHEADS), 256, flash_smem>>>();
    out_gemm<<<dim3(DMODEL / 128, MROWS / 128, 1), 256>>>(Wo, bo, out);
}

// round 7
// speedup vs baseline: 3.4924x; 3.4924x over previous
#include <cuda_runtime.h>
#include <cstdint>

#define BATCH  4
#define SEQ    2048
#define DMODEL 1024
#define NHEADS 16
#define HDIM   64
#define MROWS  (BATCH * SEQ)   // 8192

// ---------------- device scratch (no allocs allowed) ----------------
__device__ float g_Q  [(size_t)BATCH * NHEADS * SEQ * HDIM];   // [b,h,n,hd] tf32
__device__ float g_K  [(size_t)BATCH * NHEADS * SEQ * HDIM];
__device__ float g_V  [(size_t)BATCH * NHEADS * SEQ * HDIM];
__device__ float g_ctx[(size_t)MROWS * DMODEL];                // [b,n,d] tf32
__device__ float g_Xc [(size_t)MROWS * DMODEL];                // X tf32
__device__ float g_Wt [(size_t)4 * DMODEL * DMODEL];           // W^T tf32 (q,k,v,o)

// ---------------- helpers ----------------
__device__ __forceinline__ float rn_tf32(float x) {
    float r; asm("cvt.rna.tf32.f32 %0, %1;" : "=f"(r) : "f"(x)); return r;
}
__device__ __forceinline__ void cp16(uint32_t dst, const void* src) {
    asm volatile("cp.async.cg.shared.global [%0], [%1], 16;"
                 :: "r"(dst), "l"(__cvta_generic_to_global(src)) : "memory");
}
__device__ __forceinline__ uint32_t smem_u32(const void* p) {
    uint32_t a;
    asm("{ .reg .u64 t; cvta.to.shared.u64 t, %1; cvt.u32.u64 %0, t; }" : "=r"(a) : "l"(p));
    return a;
}

// m16n8k8 tf32 tensor-core mma (base PTX target — runs as HMMA on sm_103)
#define MMA_TF32(d, a, b)                                                     \
    asm volatile(                                                             \
        "mma.sync.aligned.m16n8k8.row.col.f32.tf32.tf32.f32 "                 \
        "{%0,%1,%2,%3}, {%4,%5,%6,%7}, {%8,%9}, {%0,%1,%2,%3};"               \
        : "+f"((d)[0]), "+f"((d)[1]), "+f"((d)[2]), "+f"((d)[3])              \
        : "r"((a)[0]), "r"((a)[1]), "r"((a)[2]), "r"((a)[3]),                 \
          "r"((b)[0]), "r"((b)[1]))

// ======================================================================
// GEMM via mma.sync: C[128x128] = A[128xK] * B^T   (B stored [n][k])
// 8 warps (4x2), warp tile 32x64, 2-stage cp.async, K-chunk 32.
// SMEM per stage: A[128][36] + B[128][36]  (pad 36 => frag LDS conflict-free)
// ======================================================================
#define MM_STAGE_BYTES (2 * 128 * 36 * 4)      // 36864
#define MM_SMEM_TOTAL  (2 * MM_STAGE_BYTES)    // 73728
#define MM_KSTAGES     (DMODEL / 32)           // 32

__device__ __forceinline__ void mm_issue(const float* Ag, const float* Bg,
                                         int bm, int bn, int stg,
                                         char* smem, int tid) {
    char* base = smem + (stg & 1) * MM_STAGE_BYTES;
    uint32_t sb = smem_u32(base);
    int kc0 = stg * 32;
#pragma unroll
    for (int it = 0; it < 4; it++) {
        int idx = tid + it * 256;
        int row = idx >> 3;
        int k4  = (idx & 7) << 2;
        cp16(sb + (uint32_t)(row * 36 + k4) * 4,
             Ag + (size_t)(bm + row) * DMODEL + kc0 + k4);
        cp16(sb + 18432u + (uint32_t)(row * 36 + k4) * 4,
             Bg + (size_t)(bn + row) * DMODEL + kc0 + k4);
    }
    asm volatile("cp.async.commit_group;" ::: "memory");
}

__device__ __forceinline__ void mm_mainloop(const float* Ag, const float* Bg,
                                            int bm, int bn, char* smem,
                                            float acc[2][8][4]) {
    const int tid  = threadIdx.x;
    const int lane = tid & 31;
    const int w    = tid >> 5;
    const int gr   = lane >> 2;
    const int tg   = lane & 3;
    const int rm   = (w & 3) * 32;
    const int cn   = (w >> 2) * 64;

#pragma unroll
    for (int i = 0; i < 2; i++)
#pragma unroll
        for (int j = 0; j < 8; j++)
#pragma unroll
            for (int e = 0; e < 4; e++) acc[i][j][e] = 0.f;

    mm_issue(Ag, Bg, bm, bn, 0, smem, tid);
    mm_issue(Ag, Bg, bm, bn, 1, smem, tid);

    for (int ks = 0; ks < MM_KSTAGES; ks++) {
        if (ks < MM_KSTAGES - 1) asm volatile("cp.async.wait_group 1;" ::: "memory");
        else                     asm volatile("cp.async.wait_group 0;" ::: "memory");
        __syncthreads();

        const uint32_t* As = (const uint32_t*)(smem + (ks & 1) * MM_STAGE_BYTES);
        const uint32_t* Bs = As + 4608;   // 18432 bytes / 4

#pragma unroll
        for (int kb = 0; kb < 4; kb++) {
            const int kc = kb * 8;
            uint32_t a[2][4];
#pragma unroll
            for (int mf = 0; mf < 2; mf++) {
                int r0 = rm + mf * 16 + gr;
                a[mf][0] = As[(r0)     * 36 + kc + tg];
                a[mf][1] = As[(r0 + 8) * 36 + kc + tg];
                a[mf][2] = As[(r0)     * 36 + kc + tg + 4];
                a[mf][3] = As[(r0 + 8) * 36 + kc + tg + 4];
            }
#pragma unroll
            for (int nf = 0; nf < 8; nf++) {
                int n0 = cn + nf * 8 + gr;
                uint32_t b[2];
                b[0] = Bs[n0 * 36 + kc + tg];
                b[1] = Bs[n0 * 36 + kc + tg + 4];
                MMA_TF32(acc[0][nf], a[0], b);
                MMA_TF32(acc[1][nf], a[1], b);
            }
        }
        __syncthreads();
        if (ks + 2 < MM_KSTAGES) mm_issue(Ag, Bg, bm, bn, ks + 2, smem, tid);
    }
}

// ---- QKV projection: epilogue scatters tf32-rounded to [b,h,n,hd] ----
__global__ __launch_bounds__(256) void qkv_tc() {
    extern __shared__ char smem[];
    const int tid = threadIdx.x, lane = tid & 31, w = tid >> 5;
    const int gr = lane >> 2, tg = lane & 3;
    const int rm = (w & 3) * 32, cn = (w >> 2) * 64;
    const int mat = blockIdx.z;
    const float* Bg = g_Wt + (size_t)mat * DMODEL * DMODEL;
    float* Out = (mat == 0) ? g_Q : ((mat == 1) ? g_K : g_V);
    const int bm = blockIdx.y * 128;
    const int bn = blockIdx.x * 128;

    float acc[2][8][4];
    mm_mainloop(g_Xc, Bg, bm, bn, smem, acc);

#pragma unroll
    for (int mf = 0; mf < 2; mf++) {
#pragma unroll
        for (int half = 0; half < 2; half++) {
            int r = bm + rm + mf * 16 + gr + half * 8;
            int b = r >> 11;
            int n = r & (SEQ - 1);
#pragma unroll
            for (int nf = 0; nf < 8; nf++) {
                int c  = bn + cn + nf * 8 + 2 * tg;
                int h  = c >> 6;
                int hd = c & 63;
                float2 v;
                v.x = rn_tf32(acc[mf][nf][half * 2 + 0]);
                v.y = rn_tf32(acc[mf][nf][half * 2 + 1]);
                *(float2*)&Out[(((size_t)b * NHEADS + h) * SEQ + n) * HDIM + hd] = v;
            }
        }
    }
}

// ---- output projection: out = ctx @ Wo^T' + bo ----
__global__ __launch_bounds__(256) void out_tc(const float* __restrict__ bo,
                                              float* __restrict__ Out) {
    extern __shared__ char smem[];
    const int tid = threadIdx.x, lane = tid & 31, w = tid >> 5;
    const int gr = lane >> 2, tg = lane & 3;
    const int rm = (w & 3) * 32, cn = (w >> 2) * 64;
    const int bm = blockIdx.y * 128;
    const int bn = blockIdx.x * 128;
    const float* Bg = g_Wt + (size_t)3 * DMODEL * DMODEL;

    float acc[2][8][4];
    mm_mainloop(g_ctx, Bg, bm, bn, smem, acc);

#pragma unroll
    for (int mf = 0; mf < 2; mf++) {
#pragma unroll
        for (int half = 0; half < 2; half++) {
            size_t r = bm + rm + mf * 16 + gr + half * 8;
#pragma unroll
            for (int nf = 0; nf < 8; nf++) {
                int c = bn + cn + nf * 8 + 2 * tg;
                float2 v;
                v.x = acc[mf][nf][half * 2 + 0] + bo[c];
                v.y = acc[mf][nf][half * 2 + 1] + bo[c + 1];
                *(float2*)&Out[r * DMODEL + c] = v;
            }
        }
    }
}

// ======================================================================
// Flash attention (causal) with tensor-core S=QK^T and O+=PV.
// BQ=BKV=64, 256 threads = 8 warps (4 M x 2 N), warp tile 16x32.
// SMEM tiles stride 68 (pad) => fragment LDS conflict-free.
// ======================================================================
#define SD 68

__global__ __launch_bounds__(256) void flash_attn() {
    extern __shared__ float sm[];
    float* Qs   = sm;                   // [64][68]
    float* Ks   = Qs + 64 * SD;         // [kv][d]
    float* Vs   = Ks + 64 * SD;         // [kv][d]
    float* Ps   = Vs + 64 * SD;         // [row][kv]
    float* m_s  = Ps + 64 * SD;
    float* l_s  = m_s + 64;
    float* al_s = l_s + 64;

    const int tid  = threadIdx.x;
    const int lane = tid & 31;
    const int w    = tid >> 5;
    const int gr   = lane >> 2;
    const int tg   = lane & 3;
    const int rm   = (w & 3) * 16;      // warp rows (16)
    const int cn   = (w >> 2) * 32;     // warp cols (32)

    const int qt = blockIdx.x;
    const int bh = blockIdx.y;
    const float* __restrict__ Qg = g_Q + (size_t)bh * SEQ * HDIM;
    const float* __restrict__ Kg = g_K + (size_t)bh * SEQ * HDIM;
    const float* __restrict__ Vg = g_V + (size_t)bh * SEQ * HDIM;

    // ---- load Q tile, then preload Q fragments into registers ----
    {
        const float* src = Qg + (size_t)qt * 64 * HDIM;
#pragma unroll
        for (int it = 0; it < 4; it++) {
            int idx = tid + it * 256;
            int row = idx >> 4;
            int c4  = (idx & 15) << 2;
            *(float4*)&Qs[row * SD + c4] = *(const float4*)(src + row * HDIM + c4);
        }
    }
    if (tid < 64) { m_s[tid] = -1e30f; l_s[tid] = 0.f; }
    __syncthreads();

    uint32_t qf[8][4];
    {
        const uint32_t* Qw = (const uint32_t*)Qs;
        int r0 = rm + gr;
#pragma unroll
        for (int kb = 0; kb < 8; kb++) {
            int kc = kb * 8;
            qf[kb][0] = Qw[(r0)     * SD + kc + tg];
            qf[kb][1] = Qw[(r0 + 8) * SD + kc + tg];
            qf[kb][2] = Qw[(r0)     * SD + kc + tg + 4];
            qf[kb][3] = Qw[(r0 + 8) * SD + kc + tg + 4];
        }
    }

    float oacc[4][4];
#pragma unroll
    for (int nf = 0; nf < 4; nf++)
#pragma unroll
        for (int e = 0; e < 4; e++) oacc[nf][e] = 0.f;

    const float scale = 0.125f;         // 1/sqrt(64)
    const int ktiles = qt + 1;

    for (int kt = 0; kt < ktiles; kt++) {
        __syncthreads();                 // protect Ks/Vs/Ps reuse
        // ---- load K, V tiles (row-major [kv][d]) ----
        const float* ksrc = Kg + (size_t)kt * 64 * HDIM;
        const float* vsrc = Vg + (size_t)kt * 64 * HDIM;
#pragma unroll
        for (int it = 0; it < 4; it++) {
            int idx = tid + it * 256;
            int row = idx >> 4;
            int c4  = (idx & 15) << 2;
            *(float4*)&Ks[row * SD + c4] = *(const float4*)(ksrc + row * HDIM + c4);
            *(float4*)&Vs[row * SD + c4] = *(const float4*)(vsrc + row * HDIM + c4);
        }
        __syncthreads();

        // ---- S = Q @ K^T via mma ----
        float sacc[4][4];
#pragma unroll
        for (int nf = 0; nf < 4; nf++)
#pragma unroll
            for (int e = 0; e < 4; e++) sacc[nf][e] = 0.f;

        {
            const uint32_t* Kw = (const uint32_t*)Ks;
#pragma unroll
            for (int kb = 0; kb < 8; kb++) {
                int kc = kb * 8;
#pragma unroll
                for (int nf = 0; nf < 4; nf++) {
                    int n0 = cn + nf * 8 + gr;
                    uint32_t b[2];
                    b[0] = Kw[n0 * SD + kc + tg];
                    b[1] = Kw[n0 * SD + kc + tg + 4];
                    MMA_TF32(sacc[nf], qf[kb], b);
                }
            }
        }

        // ---- scale + causal mask, store to Ps[row][kv] ----
        {
            const int qrow0 = qt * 64 + rm + gr;
            const int r0 = rm + gr;
#pragma unroll
            for (int nf = 0; nf < 4; nf++) {
                int cl = cn + nf * 8 + 2 * tg;
                int kc0 = kt * 64 + cl;
                float v0 = sacc[nf][0] * scale;
                float v1 = sacc[nf][1] * scale;
                float v2 = sacc[nf][2] * scale;
                float v3 = sacc[nf][3] * scale;
                if (kc0     > qrow0)     v0 = -1e30f;
                if (kc0 + 1 > qrow0)     v1 = -1e30f;
                if (kc0     > qrow0 + 8) v2 = -1e30f;
                if (kc0 + 1 > qrow0 + 8) v3 = -1e30f;
                *(float2*)&Ps[(r0)     * SD + cl] = make_float2(v0, v1);
                *(float2*)&Ps[(r0 + 8) * SD + cl] = make_float2(v2, v3);
            }
        }
        __syncthreads();

        // ---- online softmax: 4 threads per row ----
        {
            const int i  = tid >> 2;
            const int qq = tid & 3;
            float mt = -1e30f;
#pragma unroll
            for (int j = qq * 16; j < qq * 16 + 16; j++)
                mt = fmaxf(mt, Ps[i * SD + j]);
            mt = fmaxf(mt, __shfl_xor_sync(0xffffffffu, mt, 1));
            mt = fmaxf(mt, __shfl_xor_sync(0xffffffffu, mt, 2));
            float m_old = m_s[i];
            float mnew  = fmaxf(m_old, mt);
            float lsum  = 0.f;
#pragma unroll
            for (int j = qq * 16; j < qq * 16 + 16; j++) {
                float p = __expf(Ps[i * SD + j] - mnew);
                Ps[i * SD + j] = rn_tf32(p);
                lsum += p;
            }
            lsum += __shfl_xor_sync(0xffffffffu, lsum, 1);
            lsum += __shfl_xor_sync(0xffffffffu, lsum, 2);
            if (qq == 0) {
                float alpha = __expf(m_old - mnew);
                l_s[i]  = l_s[i] * alpha + lsum;
                m_s[i]  = mnew;
                al_s[i] = alpha;
            }
        }
        __syncthreads();

        // ---- rescale O, then O += P @ V via mma ----
        {
            float al0 = al_s[rm + gr];
            float al1 = al_s[rm + gr + 8];
#pragma unroll
            for (int nf = 0; nf < 4; nf++) {
                oacc[nf][0] *= al0; oacc[nf][1] *= al0;
                oacc[nf][2] *= al1; oacc[nf][3] *= al1;
            }
            const uint32_t* Pw = (const uint32_t*)Ps;
            const uint32_t* Vw = (const uint32_t*)Vs;
            const int r0 = rm + gr;
#pragma unroll
            for (int kb = 0; kb < 8; kb++) {
                int kc = kb * 8;
                uint32_t pa[4];
                pa[0] = Pw[(r0)     * SD + kc + tg];
                pa[1] = Pw[(r0 + 8) * SD + kc + tg];
                pa[2] = Pw[(r0)     * SD + kc + tg + 4];
                pa[3] = Pw[(r0 + 8) * SD + kc + tg + 4];
#pragma unroll
                for (int nf = 0; nf < 4; nf++) {
                    int n0 = cn + nf * 8 + gr;
                    uint32_t b[2];
                    b[0] = Vw[(kc + tg)     * SD + n0];
                    b[1] = Vw[(kc + tg + 4) * SD + n0];
                    MMA_TF32(oacc[nf], pa, b);
                }
            }
        }
    }

    // ---- epilogue: normalize, round tf32, write ctx [b,n,d] ----
    {
        const int b = bh >> 4;
        const int h = bh & 15;
        const int r0 = rm + gr;
        float inv0 = 1.f / l_s[r0];
        float inv1 = 1.f / l_s[r0 + 8];
        int n0 = qt * 64 + r0;
#pragma unroll
        for (int nf = 0; nf < 4; nf++) {
            int d = h * HDIM + cn + nf * 8 + 2 * tg;
            float2 v;
            v.x = rn_tf32(oacc[nf][0] * inv0);
            v.y = rn_tf32(oacc[nf][1] * inv0);
            *(float2*)&g_ctx[((size_t)b * SEQ + n0) * DMODEL + d] = v;
            v.x = rn_tf32(oacc[nf][2] * inv1);
            v.y = rn_tf32(oacc[nf][3] * inv1);
            *(float2*)&g_ctx[((size_t)b * SEQ + n0 + 8) * DMODEL + d] = v;
        }
    }
}

// ---------------- prep kernels: tf32 rounding (+ weight transpose) ----------------
__global__ __launch_bounds__(256) void round_x(const float4* __restrict__ X) {
    size_t i = (size_t)blockIdx.x * 256 + threadIdx.x;
    float4 v = X[i];
    v.x = rn_tf32(v.x); v.y = rn_tf32(v.y); v.z = rn_tf32(v.z); v.w = rn_tf32(v.w);
    ((float4*)g_Xc)[i] = v;
}

__global__ __launch_bounds__(256) void prep_w(const float* __restrict__ Wq,
                                              const float* __restrict__ Wk,
                                              const float* __restrict__ Wv,
                                              const float* __restrict__ Wo) {
    __shared__ float t[32][33];
    const int z = blockIdx.z;
    const float* W = (z == 0) ? Wq : (z == 1) ? Wk : (z == 2) ? Wv : Wo;
    float* Out = g_Wt + (size_t)z * DMODEL * DMODEL;
    const int n0 = blockIdx.x * 32, k0 = blockIdx.y * 32;
    const int tx = threadIdx.x & 31, ty = threadIdx.x >> 5;   // 32x8
#pragma unroll
    for (int i = 0; i < 4; i++) {
        int k = k0 + ty + i * 8;
        t[ty + i * 8][tx] = W[(size_t)k * DMODEL + n0 + tx];
    }
    __syncthreads();
#pragma unroll
    for (int i = 0; i < 4; i++) {
        int n = n0 + ty + i * 8;
        Out[(size_t)n * DMODEL + k0 + tx] = rn_tf32(t[tx][ty + i * 8]);
    }
}

// ======================================================================
extern "C" void kernel_launch(void* const* d_in, const int* in_sizes, int n_in,
                              void* d_out, int out_size) {
    (void)in_sizes; (void)n_in; (void)out_size;
    const float* x  = (const float*)d_in[0];
    const float* Wq = (const float*)d_in[1];
    const float* Wk = (const float*)d_in[2];
    const float* Wv = (const float*)d_in[3];
    const float* Wo = (const float*)d_in[4];
    const float* bo = (const float*)d_in[5];
    float* out = (float*)d_out;

    const int flash_smem = (4 * 64 * SD + 3 * 64) * (int)sizeof(float);   // 70400
    cudaFuncSetAttribute(flash_attn, cudaFuncAttributeMaxDynamicSharedMemorySize, flash_smem);
    cudaFuncSetAttribute(qkv_tc, cudaFuncAttributeMaxDynamicSharedMemorySize, MM_SMEM_TOTAL);
    cudaFuncSetAttribute(out_tc, cudaFuncAttributeMaxDynamicSharedMemorySize, MM_SMEM_TOTAL);

    round_x<<<(MROWS * DMODEL) / 4 / 256, 256>>>((const float4*)x);
    prep_w<<<dim3(32, 32, 4), 256>>>(Wq, Wk, Wv, Wo);
    qkv_tc<<<dim3(DMODEL / 128, MROWS / 128, 3), 256, MM_SMEM_TOTAL>>>();
    flash_attn<<<dim3(SEQ / 64, BATCH * NHEADS), 256, flash_smem>>>();
    out_tc<<<dim3(DMODEL / 128, MROWS / 128), 256, MM_SMEM_TOTAL>>>(bo, out);
}